// round 7
// baseline (speedup 1.0000x reference)
#include <cuda_runtime.h>
#include <cuda_fp16.h>

#define R     8192
#define D     64
#define TW    1000
#define TTOT  2000
#define NB    152     // one CTA per SM
#define NT    512     // 16 warps
#define WARPS 16
#define PINR  12      // rows pinned in SMEM per CTA (warps 0,1,2 fully pinned)

// Row partition: CTA c<136 -> 54 rows at 54c ; c>=136 -> 53 rows at 7344+53(c-136)

// d_out layout (float32): prediction[1000,64], target[1000,64],
// prediction_augment[2000,64], target_augment[2000,64]
#define PRED_OFF 0
#define TGT_OFF  (1000*64)
#define PA_OFF   (2*1000*64)
#define TA_OFF   (4*1000*64)

// ---------------- device state ----------------
__device__ __half  d_Wh16[(size_t)R * R];   // 128 MB fp16 W_h (PERMUTED layout)
__device__ float   d_WoutT[(size_t)R * D];  // W_out transposed [r][i]
__device__ float   d_h[2][R];
__device__ float   d_osub[3][8][D];
__device__ unsigned d_bar_count;
__device__ unsigned d_bar_gen;

// ---------------- prologue: fp32 -> fp16, permuted for conflict-free LDS ----
__global__ void k_convert(const float* __restrict__ Wh) {
    size_t n = (size_t)R * R / 8;
    uint4* dst = (uint4*)d_Wh16;
    for (size_t o = (size_t)blockIdx.x * blockDim.x + threadIdx.x; o < n;
         o += (size_t)gridDim.x * blockDim.x) {
        size_t r = o >> 10;
        int rem = (int)(o & 1023);
        int it = rem >> 5, lane = rem & 31;
        const float* base = Wh + r * R + it * 256 + lane * 4;
        float4 a = *(const float4*)base;
        float4 b = *(const float4*)(base + 128);
        __half2 p0 = __floats2half2_rn(a.x, a.y);
        __half2 p1 = __floats2half2_rn(a.z, a.w);
        __half2 p2 = __floats2half2_rn(b.x, b.y);
        __half2 p3 = __floats2half2_rn(b.z, b.w);
        uint4 q;
        q.x = *reinterpret_cast<unsigned*>(&p0);
        q.y = *reinterpret_cast<unsigned*>(&p1);
        q.z = *reinterpret_cast<unsigned*>(&p2);
        q.w = *reinterpret_cast<unsigned*>(&p3);
        dst[o] = q;
    }
}

// ---------------- prologue ----------------
__global__ void k_prep(const float* __restrict__ Wout,
                       const float* __restrict__ xin,
                       float* __restrict__ out) {
    int tid = blockIdx.x * blockDim.x + threadIdx.x;
    int stride = gridDim.x * blockDim.x;
    for (int i = tid; i < R * D; i += stride) {
        int r = i / D, c = i % D;
        d_WoutT[i] = Wout[(size_t)c * R + r];
    }
    for (int i = tid; i < TTOT * D; i += stride) {
        float v = xin[i];
        out[TA_OFF + i] = v;
        if (i >= TW * D) out[TGT_OFF + i - TW * D] = v;
    }
    for (int i = tid; i < R; i += stride) { d_h[0][i] = 0.f; d_h[1][i] = 0.f; }
    if (tid < 3 * 8 * D) ((float*)d_osub)[tid] = 0.f;
    if (tid == 0) { d_bar_count = 0; d_bar_gen = 0; }
}

// weight uint4 (8 halves) dotted with 8 h values given as 4 float2
__device__ __forceinline__ float dot8h(uint4 q, float2 hA0, float2 hA1,
                                       float2 hB0, float2 hB1) {
    const __half2* w = reinterpret_cast<const __half2*>(&q);
    float2 w0 = __half22float2(w[0]);
    float2 w1 = __half22float2(w[1]);
    float2 w2 = __half22float2(w[2]);
    float2 w3 = __half22float2(w[3]);
    return w0.x * hA0.x + w0.y * hA0.y + w1.x * hA1.x + w1.y * hA1.y +
           w2.x * hB0.x + w2.y * hB0.y + w3.x * hB1.x + w3.y * hB1.y;
}

// dynamic smem layout
#define SM_WC    0                               // PINR*16384 = 196608 B
#define SM_H     (PINR * R * 2)                  // 8192 halves = 16384 B
#define SM_ORED  (SM_H + R * 2)                  // 16*64 floats = 4096 B
#define SM_X     (SM_ORED + WARPS * 64 * 4)      // 64 floats = 256 B
#define SM_TOTAL (SM_X + 64 * 4)                 // 217344 B

// load h (8 fp16 values) for block itt and convert to 4 float2
#define LOADH(ITT)                                                     \
    uint2 uA = *(const uint2*)(h2s + (ITT) * 128 + lane * 2);          \
    uint2 uB = *(const uint2*)(h2s + (ITT) * 128 + lane * 2 + 64);     \
    float2 hA0 = __half22float2(*(const __half2*)&uA.x);               \
    float2 hA1 = __half22float2(*(const __half2*)&uA.y);               \
    float2 hB0 = __half22float2(*(const __half2*)&uB.x);               \
    float2 hB1 = __half22float2(*(const __half2*)&uB.y);

// ---------------- persistent ESN kernel ----------------
__global__ void __launch_bounds__(NT, 1)
k_esn(const float* __restrict__ xin,
      const float* __restrict__ Win,
      float* __restrict__ out) {
    extern __shared__ char smem[];
    __half*   wc   = (__half*)(smem + SM_WC);
    __half2*  h2s  = (__half2*)(smem + SM_H);
    float*    ored = (float*)(smem + SM_ORED);
    float*    x_sh = (float*)(smem + SM_X);

    const int tid  = threadIdx.x;
    const int lane = tid & 31;
    const int warp = tid >> 5;
    const int cta  = blockIdx.x;

    // ---- uneven row partition ----
    const int nrows = (cta < 136) ? 54 : 53;
    const int rows0 = (cta < 136) ? 54 * cta : 7344 + 53 * (cta - 136);
    const int extra = nrows - 48;                       // # of 4-row warps (5 or 6)
    const int wr    = (warp < extra) ? 4 : 3;
    const int woff  = (warp < extra) ? 4 * warp : 4 * extra + 3 * (warp - extra);
    const int grow0 = rows0 + woff;

    // ---- pin first PINR rows in SMEM ----
    {
        const uint4* src = (const uint4*)(d_Wh16 + (size_t)rows0 * R);
        uint4* dst = (uint4*)wc;
        for (int i = tid; i < PINR * (R / 8); i += NT) dst[i] = src[i];
    }

    const uint4* g0 = (const uint4*)(d_Wh16 + (size_t)(grow0 + 0) * R);
    const uint4* g1 = (const uint4*)(d_Wh16 + (size_t)(grow0 + 1) * R);
    const uint4* g2 = (const uint4*)(d_Wh16 + (size_t)(grow0 + 2) * R);
    const uint4* g3 = (const uint4*)(d_Wh16 + (size_t)(grow0 + 3) * R);
    const uint4* c0 = (const uint4*)(wc + (size_t)(woff + 0) * R);
    const uint4* c1 = (const uint4*)(wc + (size_t)(woff + 1) * R);
    const uint4* c2 = (const uint4*)(wc + (size_t)(woff + 2) * R);
    const uint4* c3 = (const uint4*)(wc + (size_t)(woff + 3) * R);
    const float* winr = Win + (size_t)grow0 * D + 2 * lane;
    const float* wt   = d_WoutT + (size_t)grow0 * D;
    __syncthreads();

    // ---- prologue prefetch for s=0 (forward direction, it=0) ----
    uint4 pf0 = {0,0,0,0}, pf1 = {0,0,0,0}, pf2 = {0,0,0,0}, pf3 = {0,0,0,0};
    if (warp >= 3) {
        pf0 = g0[lane]; pf1 = g1[lane]; pf2 = g2[lane];
        if (wr == 4) pf3 = g3[lane];
    }

    for (int s = 0; s < TTOT; ++s) {
        const bool rev = (s & 1);
        // ---- publish out(h_s), prepare x, recycle buffers ----
        if (tid < D) {
            float o = 0.f;
            if (cta == 0 || s >= TW) {
                #pragma unroll
                for (int b = 0; b < 8; ++b) o += d_osub[s % 3][b][tid];
            }
            if (cta == 0) {
                if (s >= 1 && s <= TW) out[PA_OFF + (s - 1) * D + tid] = o;
                if (s >= TW) {
                    out[PRED_OFF + (s - TW) * D + tid] = o;
                    out[PA_OFF + s * D + tid] = o;
                }
            }
            if (cta < 8) d_osub[(s + 2) % 3][cta][tid] = 0.f;
            x_sh[tid] = (s < TW) ? xin[(size_t)s * D + tid] : o;
        }
        // ---- stage h_s into shared as fp16 ----
        {
            const float4* hsrc = (const float4*)d_h[s & 1];
            uint4* hdst = (uint4*)h2s;
            for (int i = tid; i < R / 8; i += NT) {
                float4 a = hsrc[2 * i], b = hsrc[2 * i + 1];
                __half2 q0 = __floats2half2_rn(a.x, a.y);
                __half2 q1 = __floats2half2_rn(a.z, a.w);
                __half2 q2 = __floats2half2_rn(b.x, b.y);
                __half2 q3 = __floats2half2_rn(b.z, b.w);
                uint4 u;
                u.x = *reinterpret_cast<unsigned*>(&q0);
                u.y = *reinterpret_cast<unsigned*>(&q1);
                u.z = *reinterpret_cast<unsigned*>(&q2);
                u.w = *reinterpret_cast<unsigned*>(&q3);
                hdst[i] = u;
            }
        }
        __syncthreads();

        // ---- W_h @ h ----
        float acc0 = 0.f, acc1 = 0.f, acc2 = 0.f, acc3 = 0.f;
        if (warp < 3) {                 // rows 0-11: fully pinned, forward order
            #pragma unroll 4
            for (int it = 0; it < 32; ++it) {
                int idx = it * 32 + lane;
                LOADH(it)
                acc0 += dot8h(c0[idx], hA0, hA1, hB0, hB1);
                acc1 += dot8h(c1[idx], hA0, hA1, hB0, hB1);
                acc2 += dot8h(c2[idx], hA0, hA1, hB0, hB1);
                acc3 += dot8h(c3[idx], hA0, hA1, hB0, hB1);
            }
        } else if (wr == 4) {
            {   // it index 0: prefetched weights
                int itt = rev ? 31 : 0;
                LOADH(itt)
                acc0 += dot8h(pf0, hA0, hA1, hB0, hB1);
                acc1 += dot8h(pf1, hA0, hA1, hB0, hB1);
                acc2 += dot8h(pf2, hA0, hA1, hB0, hB1);
                acc3 += dot8h(pf3, hA0, hA1, hB0, hB1);
            }
            #pragma unroll 4
            for (int it = 1; it < 32; ++it) {
                int itt = rev ? (31 - it) : it;
                int idx = itt * 32 + lane;
                LOADH(itt)
                acc0 += dot8h(g0[idx], hA0, hA1, hB0, hB1);
                acc1 += dot8h(g1[idx], hA0, hA1, hB0, hB1);
                acc2 += dot8h(g2[idx], hA0, hA1, hB0, hB1);
                acc3 += dot8h(g3[idx], hA0, hA1, hB0, hB1);
            }
        } else {
            {   // it index 0: prefetched weights
                int itt = rev ? 31 : 0;
                LOADH(itt)
                acc0 += dot8h(pf0, hA0, hA1, hB0, hB1);
                acc1 += dot8h(pf1, hA0, hA1, hB0, hB1);
                acc2 += dot8h(pf2, hA0, hA1, hB0, hB1);
            }
            #pragma unroll 4
            for (int it = 1; it < 32; ++it) {
                int itt = rev ? (31 - it) : it;
                int idx = itt * 32 + lane;
                LOADH(itt)
                acc0 += dot8h(g0[idx], hA0, hA1, hB0, hB1);
                acc1 += dot8h(g1[idx], hA0, hA1, hB0, hB1);
                acc2 += dot8h(g2[idx], hA0, hA1, hB0, hB1);
            }
        }

        // ---- + W_in @ x ----
        {
            float xa = x_sh[2 * lane], xb = x_sh[2 * lane + 1];
            acc0 += winr[0]         * xa + winr[1]         * xb;
            acc1 += winr[D]         * xa + winr[D + 1]     * xb;
            acc2 += winr[2 * D]     * xa + winr[2 * D + 1] * xb;
            if (wr == 4)
                acc3 += winr[3 * D] * xa + winr[3 * D + 1] * xb;
        }
        #pragma unroll
        for (int o = 16; o; o >>= 1) {
            acc0 += __shfl_xor_sync(0xffffffffu, acc0, o);
            acc1 += __shfl_xor_sync(0xffffffffu, acc1, o);
            acc2 += __shfl_xor_sync(0xffffffffu, acc2, o);
            acc3 += __shfl_xor_sync(0xffffffffu, acc3, o);
        }
        // ---- lane-parallel tanh + h store + aug ----
        float pre = (lane == 0) ? acc0 : (lane == 1) ? acc1
                  : (lane == 2) ? acc2 : acc3;
        float hv = tanhf(pre);
        float av = 0.f;
        if (lane < wr) {
            d_h[(s + 1) & 1][grow0 + lane] = hv;
            av = (((grow0 + lane) & 1) == 0) ? hv * hv : hv;
        }
        float a0 = __shfl_sync(0xffffffffu, av, 0);
        float a1 = __shfl_sync(0xffffffffu, av, 1);
        float a2 = __shfl_sync(0xffffffffu, av, 2);
        float a3 = __shfl_sync(0xffffffffu, av, 3);

        // ---- fused readout partials ----
        float p0 = wt[lane]      * a0 + wt[D + lane]      * a1 + wt[2 * D + lane]      * a2;
        float p1 = wt[32 + lane] * a0 + wt[D + 32 + lane] * a1 + wt[2 * D + 32 + lane] * a2;
        if (wr == 4) {
            p0 += wt[3 * D + lane]      * a3;
            p1 += wt[3 * D + 32 + lane] * a3;
        }
        ored[warp * 64 + lane]      = p0;
        ored[warp * 64 + 32 + lane] = p1;
        __syncthreads();
        if (tid < D) {
            float sum = 0.f;
            #pragma unroll
            for (int w = 0; w < WARPS; ++w) sum += ored[w * 64 + tid];
            atomicAdd(&d_osub[(s + 1) % 3][cta & 7][tid], sum);
        }

        // ---- grid barrier, split: arrive -> prefetch next step -> wait ----
        __threadfence();
        __syncthreads();
        unsigned g = 0, arr = 0;
        if (tid == 0) {
            g = *(volatile unsigned*)&d_bar_gen;
            arr = atomicAdd(&d_bar_count, 1u);
        }
        if (warp >= 3 && s + 1 < TTOT) {   // prefetch it0 of next step during wait
            int itn = ((s + 1) & 1) ? 31 : 0;
            int xi = itn * 32 + lane;
            pf0 = g0[xi]; pf1 = g1[xi]; pf2 = g2[xi];
            if (wr == 4) pf3 = g3[xi];
        }
        if (tid == 0) {
            volatile unsigned* vgen = (volatile unsigned*)&d_bar_gen;
            if (arr == NB - 1) {
                *(volatile unsigned*)&d_bar_count = 0;
                __threadfence();
                *vgen = g + 1;
            } else {
                while (*vgen == g) { }
            }
            __threadfence();
        }
        __syncthreads();
    }
}

// ---------------- launch ----------------
extern "C" void kernel_launch(void* const* d_in, const int* in_sizes, int n_in,
                              void* d_out, int out_size) {
    const float* xin  = (const float*)d_in[0];
    const float* Win  = (const float*)d_in[1];
    const float* Whf  = (const float*)d_in[2];
    const float* Wout = (const float*)d_in[3];
    float* out = (float*)d_out;

    static bool attr_set = false;
    if (!attr_set) {
        cudaFuncSetAttribute(k_esn, cudaFuncAttributeMaxDynamicSharedMemorySize, SM_TOTAL);
        attr_set = true;
    }

    k_convert<<<4096, 256>>>(Whf);
    k_prep<<<1024, 256>>>(Wout, xin, out);
    k_esn<<<NB, NT, SM_TOTAL>>>(xin, Win, out);
}